// round 3
// baseline (speedup 1.0000x reference)
#include <cuda_runtime.h>
#include <math_constants.h>

#define TSEQ   2048
#define DMODEL 1024
#define NHEAD  16
#define DK     64
#define BATCH  2
#define MROWS  (BATCH * TSEQ)   // 4096

// ---------------------------------------------------------------------------
// Scratch (allocation-free: __device__ globals, referenced directly)
// ---------------------------------------------------------------------------
__device__ float g_Q[BATCH * NHEAD * TSEQ * DK];     // [B,H,T,dk]
__device__ float g_K[BATCH * NHEAD * TSEQ * DK];
__device__ float g_V[BATCH * NHEAD * TSEQ * DK];
__device__ float g_ctx[(size_t)MROWS * DMODEL];      // [B,T,D]

// ---------------------------------------------------------------------------
// Fused QKV NT GEMM: for z in {Q,K,V}: C_z[m,n] = sum_k x[m,k]*W_z[n,k] + b_z[n]
// scattered into [B,H,T,dk] head-major scratch.
// 128x128 tile, BK=16, 256 threads, 8x8 per-thread register tile.
// ---------------------------------------------------------------------------
__global__ __launch_bounds__(256) void qkv_gemm_kernel(
    const float* __restrict__ A,
    const float* __restrict__ Wq, const float* __restrict__ bq,
    const float* __restrict__ Wk, const float* __restrict__ bk,
    const float* __restrict__ Wv, const float* __restrict__ bv)
{
    const float* W;
    const float* bias;
    float* C;
    if (blockIdx.z == 0)      { W = Wq; bias = bq; C = g_Q; }
    else if (blockIdx.z == 1) { W = Wk; bias = bk; C = g_K; }
    else                      { W = Wv; bias = bv; C = g_V; }

    __shared__ float As[16][132];
    __shared__ float Bs[16][132];

    const int bm = blockIdx.y * 128;
    const int bn = blockIdx.x * 128;
    const int t  = threadIdx.x;
    const int tx = t & 15;
    const int ty = t >> 4;

    float acc[8][8];
#pragma unroll
    for (int i = 0; i < 8; i++)
#pragma unroll
        for (int j = 0; j < 8; j++) acc[i][j] = 0.f;

    for (int k0 = 0; k0 < DMODEL; k0 += 16) {
#pragma unroll
        for (int i = 0; i < 2; i++) {
            int idx = t + 256 * i;          // 0..511 float4 slots
            int row = idx >> 2;             // 0..127
            int c4  = (idx & 3) * 4;        // 0,4,8,12
            float4 a = *(const float4*)(A + (size_t)(bm + row) * DMODEL + k0 + c4);
            As[c4 + 0][row] = a.x; As[c4 + 1][row] = a.y;
            As[c4 + 2][row] = a.z; As[c4 + 3][row] = a.w;
            float4 b = *(const float4*)(W + (size_t)(bn + row) * DMODEL + k0 + c4);
            Bs[c4 + 0][row] = b.x; Bs[c4 + 1][row] = b.y;
            Bs[c4 + 2][row] = b.z; Bs[c4 + 3][row] = b.w;
        }
        __syncthreads();

#pragma unroll
        for (int k = 0; k < 16; k++) {
            float af[8], bf[8];
            *(float4*)&af[0] = *(float4*)&As[k][ty * 8];
            *(float4*)&af[4] = *(float4*)&As[k][ty * 8 + 4];
            *(float4*)&bf[0] = *(float4*)&Bs[k][tx * 8];
            *(float4*)&bf[4] = *(float4*)&Bs[k][tx * 8 + 4];
#pragma unroll
            for (int i = 0; i < 8; i++)
#pragma unroll
                for (int j = 0; j < 8; j++)
                    acc[i][j] += af[i] * bf[j];
        }
        __syncthreads();
    }

#pragma unroll
    for (int i = 0; i < 8; i++) {
        int m   = bm + ty * 8 + i;
        int b   = m >> 11;            // T = 2048
        int tok = m & (TSEQ - 1);
#pragma unroll
        for (int j = 0; j < 8; j++) {
            int n = bn + tx * 8 + j;
            float v = acc[i][j] + bias[n];
            int h = n >> 6;           // dk = 64
            int d = n & 63;
            C[((((size_t)b * NHEAD + h) * TSEQ + tok) << 6) + d] = v;
        }
    }
}

// ---------------------------------------------------------------------------
// Output projection NT GEMM: out[m,n] = g_ctx[m,:] . Wo[n,:] + bo[n]
// ---------------------------------------------------------------------------
__global__ __launch_bounds__(256) void out_gemm_kernel(
    const float* __restrict__ W, const float* __restrict__ bias,
    float* __restrict__ C)
{
    const float* __restrict__ A = g_ctx;

    __shared__ float As[16][132];
    __shared__ float Bs[16][132];

    const int bm = blockIdx.y * 128;
    const int bn = blockIdx.x * 128;
    const int t  = threadIdx.x;
    const int tx = t & 15;
    const int ty = t >> 4;

    float acc[8][8];
#pragma unroll
    for (int i = 0; i < 8; i++)
#pragma unroll
        for (int j = 0; j < 8; j++) acc[i][j] = 0.f;

    for (int k0 = 0; k0 < DMODEL; k0 += 16) {
#pragma unroll
        for (int i = 0; i < 2; i++) {
            int idx = t + 256 * i;
            int row = idx >> 2;
            int c4  = (idx & 3) * 4;
            float4 a = *(const float4*)(A + (size_t)(bm + row) * DMODEL + k0 + c4);
            As[c4 + 0][row] = a.x; As[c4 + 1][row] = a.y;
            As[c4 + 2][row] = a.z; As[c4 + 3][row] = a.w;
            float4 b = *(const float4*)(W + (size_t)(bn + row) * DMODEL + k0 + c4);
            Bs[c4 + 0][row] = b.x; Bs[c4 + 1][row] = b.y;
            Bs[c4 + 2][row] = b.z; Bs[c4 + 3][row] = b.w;
        }
        __syncthreads();

#pragma unroll
        for (int k = 0; k < 16; k++) {
            float af[8], bf[8];
            *(float4*)&af[0] = *(float4*)&As[k][ty * 8];
            *(float4*)&af[4] = *(float4*)&As[k][ty * 8 + 4];
            *(float4*)&bf[0] = *(float4*)&Bs[k][tx * 8];
            *(float4*)&bf[4] = *(float4*)&Bs[k][tx * 8 + 4];
#pragma unroll
            for (int i = 0; i < 8; i++)
#pragma unroll
                for (int j = 0; j < 8; j++)
                    acc[i][j] += af[i] * bf[j];
        }
        __syncthreads();
    }

#pragma unroll
    for (int i = 0; i < 8; i++) {
        int m = bm + ty * 8 + i;
#pragma unroll
        for (int j = 0; j < 8; j++) {
            int n = bn + tx * 8 + j;
            C[(size_t)m * DMODEL + n] = acc[i][j] + bias[n];
        }
    }
}

// ---------------------------------------------------------------------------
// Flash-style attention, full (non-causal) softmax(QK^T/8)V per head.
// CTA: 64 q-rows x dk=64. 256 threads, 4x4 per-thread tiles.
// smem: Qs[64][68] (Q^T, pre-scaled), KVs[64][68] (K^T then V), Ps[64][64].
// Online softmax (shift-invariant => identical result to reference's naive
// softmax). Writes ctx in [B,T,D] so output projection is a plain GEMM.
// ---------------------------------------------------------------------------
#define ATTN_SMEM (2 * 64 * 68 * 4 + 64 * 64 * 4)   // 51,200 bytes

__global__ __launch_bounds__(256) void attn_kernel()
{
    extern __shared__ float sm[];
    float* Qs  = sm;                 // [64][68], Qs[kk][row]
    float* KVs = sm + 64 * 68;       // [64][68], Ks[kk][col] then Vs[tok][col]
    float* Ps  = sm + 2 * 64 * 68;   // [64][64]

    const int qt = blockIdx.x;
    const int h  = blockIdx.y;
    const int b  = blockIdx.z;
    const int bh = b * NHEAD + h;
    const float* Qp = g_Q + (size_t)bh * TSEQ * DK + (size_t)qt * 64 * DK;
    const float* Kp = g_K + (size_t)bh * TSEQ * DK;
    const float* Vp = g_V + (size_t)bh * TSEQ * DK;

    const int t  = threadIdx.x;
    const int tx = t & 15;
    const int ty = t >> 4;

    // Load Q tile transposed + scaled by 1/sqrt(dk) = 1/8
#pragma unroll
    for (int i = 0; i < 4; i++) {
        int idx = t + 256 * i;         // 0..1023 float4 slots
        int row = idx >> 4;            // 0..63
        int c   = (idx & 15) * 4;      // 0..60
        float4 q = *(const float4*)(Qp + row * DK + c);
        Qs[(c + 0) * 68 + row] = q.x * 0.125f;
        Qs[(c + 1) * 68 + row] = q.y * 0.125f;
        Qs[(c + 2) * 68 + row] = q.z * 0.125f;
        Qs[(c + 3) * 68 + row] = q.w * 0.125f;
    }

    float acc[4][4];
    float mrow[4], lrow[4];
#pragma unroll
    for (int i = 0; i < 4; i++) {
        mrow[i] = -1e30f;
        lrow[i] = 0.f;
#pragma unroll
        for (int j = 0; j < 4; j++) acc[i][j] = 0.f;
    }

    for (int kt = 0; kt < TSEQ / 64; kt++) {
        __syncthreads();   // prior-iter O compute done reading KVs/Ps
        const float* Kt = Kp + (size_t)kt * 64 * DK;
        const float* Vt = Vp + (size_t)kt * 64 * DK;

        // K tile, stored transposed: KVs[kk][col]
#pragma unroll
        for (int i = 0; i < 4; i++) {
            int idx = t + 256 * i;
            int row = idx >> 4;
            int c   = (idx & 15) * 4;
            float4 k4 = *(const float4*)(Kt + row * DK + c);
            KVs[(c + 0) * 68 + row] = k4.x;
            KVs[(c + 1) * 68 + row] = k4.y;
            KVs[(c + 2) * 68 + row] = k4.z;
            KVs[(c + 3) * 68 + row] = k4.w;
        }
        __syncthreads();   // Q (first iter) + K visible

        // S = (Q/8) K^T   (4x4 per thread)
        float s[4][4];
#pragma unroll
        for (int i = 0; i < 4; i++)
#pragma unroll
            for (int j = 0; j < 4; j++) s[i][j] = 0.f;

#pragma unroll 8
        for (int kk = 0; kk < 64; kk++) {
            float4 q4 = *(float4*)&Qs[kk * 68 + ty * 4];
            float4 k4 = *(float4*)&KVs[kk * 68 + tx * 4];
            float qa[4] = {q4.x, q4.y, q4.z, q4.w};
            float ka[4] = {k4.x, k4.y, k4.z, k4.w};
#pragma unroll
            for (int i = 0; i < 4; i++)
#pragma unroll
                for (int j = 0; j < 4; j++)
                    s[i][j] += qa[i] * ka[j];
        }
        __syncthreads();   // everyone done reading K from KVs

        // V tile, natural layout into the same buffer: KVs[tok][col]
#pragma unroll
        for (int i = 0; i < 4; i++) {
            int idx = t + 256 * i;
            int row = idx >> 4;
            int c   = (idx & 15) * 4;
            *(float4*)&KVs[row * 68 + c] = *(const float4*)(Vt + row * DK + c);
        }

        // Online softmax on the 4 rows this thread-row-group owns
#pragma unroll
        for (int i = 0; i < 4; i++) {
            float tm = fmaxf(fmaxf(s[i][0], s[i][1]), fmaxf(s[i][2], s[i][3]));
#pragma unroll
            for (int off = 1; off < 16; off <<= 1)
                tm = fmaxf(tm, __shfl_xor_sync(0xffffffffu, tm, off));
            float mnew  = fmaxf(mrow[i], tm);
            float alpha = __expf(mrow[i] - mnew);
            mrow[i] = mnew;

            float p0 = __expf(s[i][0] - mnew);
            float p1 = __expf(s[i][1] - mnew);
            float p2 = __expf(s[i][2] - mnew);
            float p3 = __expf(s[i][3] - mnew);
            float rs = p0 + p1 + p2 + p3;
#pragma unroll
            for (int off = 1; off < 16; off <<= 1)
                rs += __shfl_xor_sync(0xffffffffu, rs, off);

            lrow[i] = lrow[i] * alpha + rs;
#pragma unroll
            for (int j = 0; j < 4; j++) acc[i][j] *= alpha;

            *(float4*)&Ps[(ty * 4 + i) * 64 + tx * 4] = make_float4(p0, p1, p2, p3);
        }
        __syncthreads();   // V + P ready

        // O += P V   (4x4 per thread)
#pragma unroll 8
        for (int kk = 0; kk < 64; kk++) {
            float4 v4 = *(float4*)&KVs[kk * 68 + tx * 4];
            float va[4] = {v4.x, v4.y, v4.z, v4.w};
            float pi[4];
#pragma unroll
            for (int i = 0; i < 4; i++) pi[i] = Ps[(ty * 4 + i) * 64 + kk];
#pragma unroll
            for (int i = 0; i < 4; i++)
#pragma unroll
                for (int j = 0; j < 4; j++)
                    acc[i][j] += pi[i] * va[j];
        }
    }

    // Normalize and write ctx in [B,T,D] layout
#pragma unroll
    for (int i = 0; i < 4; i++) {
        float inv = 1.f / lrow[i];
        int tok = qt * 64 + ty * 4 + i;
        float4 o = make_float4(acc[i][0] * inv, acc[i][1] * inv,
                               acc[i][2] * inv, acc[i][3] * inv);
        *(float4*)(g_ctx + (size_t)(b * TSEQ + tok) * DMODEL + h * DK + tx * 4) = o;
    }
}

// ---------------------------------------------------------------------------
// Launch
// ---------------------------------------------------------------------------
extern "C" void kernel_launch(void* const* d_in, const int* in_sizes, int n_in,
                              void* d_out, int out_size)
{
    const float* x  = (const float*)d_in[0];
    const float* Wq = (const float*)d_in[1];
    const float* bq = (const float*)d_in[2];
    const float* Wk = (const float*)d_in[3];
    const float* bk = (const float*)d_in[4];
    const float* Wv = (const float*)d_in[5];
    const float* bv = (const float*)d_in[6];
    const float* Wo = (const float*)d_in[7];
    const float* bo = (const float*)d_in[8];
    float* out = (float*)d_out;

    dim3 gqkv(DMODEL / 128, MROWS / 128, 3);   // (8, 32, 3)
    qkv_gemm_kernel<<<gqkv, 256>>>(x, Wq, bq, Wk, bk, Wv, bv);

    cudaFuncSetAttribute(attn_kernel,
                         cudaFuncAttributeMaxDynamicSharedMemorySize, ATTN_SMEM);
    attn_kernel<<<dim3(TSEQ / 64, NHEAD, BATCH), 256, ATTN_SMEM>>>();

    dim3 go(DMODEL / 128, MROWS / 128);        // (8, 32)
    out_gemm_kernel<<<go, 256>>>(Wo, bo, out);
}

// round 5
// speedup vs baseline: 1.3688x; 1.3688x over previous
#include <cuda_runtime.h>
#include <cuda_bf16.h>
#include <cstdint>

#define TSEQ   2048
#define DMODEL 1024
#define NHEAD  16
#define DK     64
#define BATCH  2
#define MROWS  (BATCH * TSEQ)   // 4096

// ===========================================================================
// Baseline-ISA helpers (cp.async / ldmatrix / mma.sync — all sm_80+ PTX)
// ===========================================================================
__device__ __forceinline__ uint32_t smem_u32_of(const void* p) {
    uint32_t a;
    asm("{ .reg .u64 t; cvta.to.shared.u64 t, %1; cvt.u32.u64 %0, t; }"
        : "=r"(a) : "l"(p));
    return a;
}

#define CP_ASYNC16(saddr, gptr) \
    asm volatile("cp.async.cg.shared.global [%0], [%1], 16;" \
        :: "r"(saddr), "l"(gptr) : "memory")
#define CP_COMMIT() asm volatile("cp.async.commit_group;" ::: "memory")
#define CP_WAIT1()  asm volatile("cp.async.wait_group 1;" ::: "memory")
#define CP_WAIT0()  asm volatile("cp.async.wait_group 0;" ::: "memory")

#define LDMATRIX_X4(r0, r1, r2, r3, addr) \
    asm volatile("ldmatrix.sync.aligned.m8n8.x4.shared.b16 {%0,%1,%2,%3}, [%4];" \
        : "=r"(r0), "=r"(r1), "=r"(r2), "=r"(r3) : "r"(addr))

#define MMA16816(d, a, b0, b1) \
    asm volatile("mma.sync.aligned.m16n8k16.row.col.f32.bf16.bf16.f32 " \
        "{%0,%1,%2,%3}, {%4,%5,%6,%7}, {%8,%9}, {%0,%1,%2,%3};" \
        : "+f"((d)[0]), "+f"((d)[1]), "+f"((d)[2]), "+f"((d)[3]) \
        : "r"((a)[0]), "r"((a)[1]), "r"((a)[2]), "r"((a)[3]), \
          "r"(b0), "r"(b1))

// ===========================================================================
// Scratch (__device__ globals)
// ===========================================================================
__device__ float g_Q[BATCH * NHEAD * TSEQ * DK];     // [B,H,T,dk] fp32
__device__ float g_K[BATCH * NHEAD * TSEQ * DK];
__device__ float g_V[BATCH * NHEAD * TSEQ * DK];
__device__ __nv_bfloat16 g_xh[(size_t)MROWS * DMODEL];     // x split
__device__ __nv_bfloat16 g_xl[(size_t)MROWS * DMODEL];
__device__ __nv_bfloat16 g_Wh[4][(size_t)DMODEL * DMODEL]; // Wq,Wk,Wv,Wo split
__device__ __nv_bfloat16 g_Wl[4][(size_t)DMODEL * DMODEL];
__device__ __nv_bfloat16 g_ch[(size_t)MROWS * DMODEL];     // ctx split
__device__ __nv_bfloat16 g_cl[(size_t)MROWS * DMODEL];

// ===========================================================================
// fp32 -> bf16 hi/lo split of x and the four weight matrices
// ===========================================================================
__global__ __launch_bounds__(256) void convert_kernel(
    const float* __restrict__ x,
    const float* __restrict__ Wq, const float* __restrict__ Wk,
    const float* __restrict__ Wv, const float* __restrict__ Wo)
{
    const float* src; __nv_bfloat16 *hi, *lo; size_t n;
    int z = blockIdx.y;
    if (z == 0)      { src = x;  hi = g_xh;    lo = g_xl;    n = (size_t)MROWS * DMODEL; }
    else if (z == 1) { src = Wq; hi = g_Wh[0]; lo = g_Wl[0]; n = (size_t)DMODEL * DMODEL; }
    else if (z == 2) { src = Wk; hi = g_Wh[1]; lo = g_Wl[1]; n = (size_t)DMODEL * DMODEL; }
    else if (z == 3) { src = Wv; hi = g_Wh[2]; lo = g_Wl[2]; n = (size_t)DMODEL * DMODEL; }
    else             { src = Wo; hi = g_Wh[3]; lo = g_Wl[3]; n = (size_t)DMODEL * DMODEL; }

    size_t i = ((size_t)blockIdx.x * 256 + threadIdx.x) * 4;
    if (i >= n) return;
    float4 v = *(const float4*)(src + i);
    __nv_bfloat16 h0 = __float2bfloat16(v.x), h1 = __float2bfloat16(v.y);
    __nv_bfloat16 h2 = __float2bfloat16(v.z), h3 = __float2bfloat16(v.w);
    __nv_bfloat16 l0 = __float2bfloat16(v.x - __bfloat162float(h0));
    __nv_bfloat16 l1 = __float2bfloat16(v.y - __bfloat162float(h1));
    __nv_bfloat16 l2 = __float2bfloat16(v.z - __bfloat162float(h2));
    __nv_bfloat16 l3 = __float2bfloat16(v.w - __bfloat162float(h3));
    __nv_bfloat162* ph = (__nv_bfloat162*)(hi + i);
    __nv_bfloat162* pl = (__nv_bfloat162*)(lo + i);
    ph[0] = __nv_bfloat162(h0, h1); ph[1] = __nv_bfloat162(h2, h3);
    pl[0] = __nv_bfloat162(l0, l1); pl[1] = __nv_bfloat162(l2, l3);
}

// ===========================================================================
// mma.sync bf16x3 GEMM: C[m,n] = sum_k A[m,k]*W[n,k] + bias[n]
// BM=128, BN=64, BK=32, 256 threads (8 warps: 4 in M x 2 in N; 32x32/warp).
// smem per stage: Ah/Al [128][40] bf16, Bh/Bl [64][40] bf16 (pad-40 stride).
// 2-stage cp.async pipeline. fp32 accum, 3 passes (hh, hl, lh).
// mode 0: z-indexed QKV, scatter to [B,H,T,dk]. mode 1: O-proj, plain [M,N].
// ===========================================================================
#define STRIDE   40                                  // bf16 elems per smem row
#define SA_H     0
#define SA_L     (128 * STRIDE * 2)                  // 10240
#define SB_H     (2 * 128 * STRIDE * 2)              // 20480
#define SB_L     (SB_H + 64 * STRIDE * 2)            // 25600
#define STAGE_B  (SB_L + 64 * STRIDE * 2)            // 30720
#define GEMM_SMEM (2 * STAGE_B)                      // 61440

__device__ __forceinline__ void issue_stage(
    uint32_t sbase, const __nv_bfloat16* Ah, const __nv_bfloat16* Al,
    const __nv_bfloat16* Bh, const __nv_bfloat16* Bl, int k0, int tid)
{
#pragma unroll
    for (int i = 0; i < 2; i++) {
        int idx = tid + 256 * i;            // 0..511
        int row = idx >> 2;                 // 0..127
        int c8  = (idx & 3) * 8;            // 0,8,16,24 bf16
        uint32_t so = (uint32_t)(row * STRIDE + c8) * 2;
        size_t   go = (size_t)row * DMODEL + k0 + c8;
        CP_ASYNC16(sbase + SA_H + so, Ah + go);
        CP_ASYNC16(sbase + SA_L + so, Al + go);
    }
    {
        int idx = tid;                      // 0..255
        int row = idx >> 2;                 // 0..63
        int c8  = (idx & 3) * 8;
        uint32_t so = (uint32_t)(row * STRIDE + c8) * 2;
        size_t   go = (size_t)row * DMODEL + k0 + c8;
        CP_ASYNC16(sbase + SB_H + so, Bh + go);
        CP_ASYNC16(sbase + SB_L + so, Bl + go);
    }
}

__global__ __launch_bounds__(256, 2) void mma_gemm_kernel(
    const float* __restrict__ b0, const float* __restrict__ b1,
    const float* __restrict__ b2, float* __restrict__ outp, int mode)
{
    extern __shared__ char smem[];
    const uint32_t sb = smem_u32_of(smem);
    const int tid  = threadIdx.x;
    const int wid  = tid >> 5;
    const int lane = tid & 31;
    const int wm   = wid & 3;       // warp M position (0..3) -> 32 rows each
    const int wn   = wid >> 2;      // warp N position (0..1) -> 32 cols each

    const int bm = blockIdx.y * 128;
    const int bn = blockIdx.x * 64;

    const __nv_bfloat16 *Ah, *Al, *Bh, *Bl;
    const float* bias;
    float* C;
    if (mode == 0) {
        int z = blockIdx.z;
        Ah = g_xh; Al = g_xl;
        Bh = g_Wh[z]; Bl = g_Wl[z];
        bias = (z == 0) ? b0 : (z == 1) ? b1 : b2;
        C = (z == 0) ? g_Q : (z == 1) ? g_K : g_V;
    } else {
        Ah = g_ch; Al = g_cl;
        Bh = g_Wh[3]; Bl = g_Wl[3];
        bias = b0;
        C = outp;
    }
    const __nv_bfloat16* Abase_h = Ah + (size_t)bm * DMODEL;
    const __nv_bfloat16* Abase_l = Al + (size_t)bm * DMODEL;
    const __nv_bfloat16* Bbase_h = Bh + (size_t)bn * DMODEL;
    const __nv_bfloat16* Bbase_l = Bl + (size_t)bn * DMODEL;

    float acc[2][4][4];
#pragma unroll
    for (int mt = 0; mt < 2; mt++)
#pragma unroll
        for (int nt = 0; nt < 4; nt++)
#pragma unroll
            for (int r = 0; r < 4; r++) acc[mt][nt][r] = 0.f;

    // Prologue: stage 0
    issue_stage(sb, Abase_h, Abase_l, Bbase_h, Bbase_l, 0, tid);
    CP_COMMIT();

    const int NCHUNK = DMODEL / 32;   // 32
    for (int c = 0; c < NCHUNK; c++) {
        if (c + 1 < NCHUNK) {
            issue_stage(sb + ((c + 1) & 1) * STAGE_B,
                        Abase_h, Abase_l, Bbase_h, Bbase_l, (c + 1) * 32, tid);
            CP_COMMIT();
            CP_WAIT1();
        } else {
            CP_WAIT0();
        }
        __syncthreads();

        const uint32_t st = sb + (c & 1) * STAGE_B;
#pragma unroll
        for (int ks = 0; ks < 2; ks++) {
            // A fragments (hi & lo) for 2 m-tiles of 16
            uint32_t ah[2][4], al[2][4];
#pragma unroll
            for (int mt = 0; mt < 2; mt++) {
                int rowb = wm * 32 + mt * 16;
                uint32_t ao = st + SA_H +
                    (uint32_t)((rowb + (lane & 15)) * STRIDE + ks * 16 + (lane >> 4) * 8) * 2;
                LDMATRIX_X4(ah[mt][0], ah[mt][1], ah[mt][2], ah[mt][3], ao);
                uint32_t lo_ = ao + (SA_L - SA_H);
                LDMATRIX_X4(al[mt][0], al[mt][1], al[mt][2], al[mt][3], lo_);
            }
            // B fragments (hi & lo): 2 x ldmatrix.x4, each covers 16 n
            uint32_t bh[8], bl[8];
#pragma unroll
            for (int p = 0; p < 2; p++) {
                int nb = wn * 32 + p * 16;
                uint32_t bo = st + SB_H +
                    (uint32_t)((nb + (lane & 7) + ((lane >> 4) & 1) * 8) * STRIDE
                               + ks * 16 + ((lane >> 3) & 1) * 8) * 2;
                LDMATRIX_X4(bh[p * 4 + 0], bh[p * 4 + 1], bh[p * 4 + 2], bh[p * 4 + 3], bo);
                uint32_t bo2 = bo + (SB_L - SB_H);
                LDMATRIX_X4(bl[p * 4 + 0], bl[p * 4 + 1], bl[p * 4 + 2], bl[p * 4 + 3], bo2);
            }
#pragma unroll
            for (int mt = 0; mt < 2; mt++)
#pragma unroll
                for (int nt = 0; nt < 4; nt++) {
                    MMA16816(acc[mt][nt], ah[mt], bh[nt * 2], bh[nt * 2 + 1]);
                    MMA16816(acc[mt][nt], ah[mt], bl[nt * 2], bl[nt * 2 + 1]);
                    MMA16816(acc[mt][nt], al[mt], bh[nt * 2], bh[nt * 2 + 1]);
                }
        }
        __syncthreads();
    }

    // Epilogue: acc -> C (+bias). Thread holds (r,c),(r,c+1),(r+8,c),(r+8,c+1).
#pragma unroll
    for (int mt = 0; mt < 2; mt++) {
#pragma unroll
        for (int nt = 0; nt < 4; nt++) {
            int m0 = bm + wm * 32 + mt * 16 + (lane >> 2);
            int n  = bn + wn * 32 + nt * 8 + (lane & 3) * 2;
            float bv0 = __ldg(bias + n), bv1 = __ldg(bias + n + 1);
#pragma unroll
            for (int half = 0; half < 2; half++) {
                int m = m0 + half * 8;
                float2 o = make_float2(acc[mt][nt][half * 2 + 0] + bv0,
                                       acc[mt][nt][half * 2 + 1] + bv1);
                if (mode == 0) {
                    int b   = m >> 11;
                    int tok = m & (TSEQ - 1);
                    int h   = n >> 6;
                    int d   = n & 63;
                    *(float2*)(C + ((((size_t)b * NHEAD + h) * TSEQ + tok) << 6) + d) = o;
                } else {
                    *(float2*)(C + (size_t)m * DMODEL + n) = o;
                }
            }
        }
    }
}

// ===========================================================================
// Flash-style attention (fp32, verified R3); ctx written as bf16 hi/lo split.
// ===========================================================================
#define ATTN_SMEM (2 * 64 * 68 * 4 + 64 * 64 * 4)   // 51,200 bytes

__global__ __launch_bounds__(256) void attn_kernel()
{
    extern __shared__ float sm[];
    float* Qs  = sm;                 // [64][68], Qs[kk][row]
    float* KVs = sm + 64 * 68;       // [64][68], Ks[kk][col] then Vs[tok][col]
    float* Ps  = sm + 2 * 64 * 68;   // [64][64]

    const int qt = blockIdx.x;
    const int h  = blockIdx.y;
    const int b  = blockIdx.z;
    const int bh = b * NHEAD + h;
    const float* Qp = g_Q + (size_t)bh * TSEQ * DK + (size_t)qt * 64 * DK;
    const float* Kp = g_K + (size_t)bh * TSEQ * DK;
    const float* Vp = g_V + (size_t)bh * TSEQ * DK;

    const int t  = threadIdx.x;
    const int tx = t & 15;
    const int ty = t >> 4;

#pragma unroll
    for (int i = 0; i < 4; i++) {
        int idx = t + 256 * i;
        int row = idx >> 4;
        int c   = (idx & 15) * 4;
        float4 q = *(const float4*)(Qp + row * DK + c);
        Qs[(c + 0) * 68 + row] = q.x * 0.125f;
        Qs[(c + 1) * 68 + row] = q.y * 0.125f;
        Qs[(c + 2) * 68 + row] = q.z * 0.125f;
        Qs[(c + 3) * 68 + row] = q.w * 0.125f;
    }

    float acc[4][4];
    float mrow[4], lrow[4];
#pragma unroll
    for (int i = 0; i < 4; i++) {
        mrow[i] = -1e30f; lrow[i] = 0.f;
#pragma unroll
        for (int j = 0; j < 4; j++) acc[i][j] = 0.f;
    }

    for (int kt = 0; kt < TSEQ / 64; kt++) {
        __syncthreads();
        const float* Kt = Kp + (size_t)kt * 64 * DK;
        const float* Vt = Vp + (size_t)kt * 64 * DK;

#pragma unroll
        for (int i = 0; i < 4; i++) {
            int idx = t + 256 * i;
            int row = idx >> 4;
            int c   = (idx & 15) * 4;
            float4 k4 = *(const float4*)(Kt + row * DK + c);
            KVs[(c + 0) * 68 + row] = k4.x;
            KVs[(c + 1) * 68 + row] = k4.y;
            KVs[(c + 2) * 68 + row] = k4.z;
            KVs[(c + 3) * 68 + row] = k4.w;
        }
        __syncthreads();

        float s[4][4];
#pragma unroll
        for (int i = 0; i < 4; i++)
#pragma unroll
            for (int j = 0; j < 4; j++) s[i][j] = 0.f;

#pragma unroll 8
        for (int kk = 0; kk < 64; kk++) {
            float4 q4 = *(float4*)&Qs[kk * 68 + ty * 4];
            float4 k4 = *(float4*)&KVs[kk * 68 + tx * 4];
            float qa[4] = {q4.x, q4.y, q4.z, q4.w};
            float ka[4] = {k4.x, k4.y, k4.z, k4.w};
#pragma unroll
            for (int i = 0; i < 4; i++)
#pragma unroll
                for (int j = 0; j < 4; j++)
                    s[i][j] += qa[i] * ka[j];
        }
        __syncthreads();

#pragma unroll
        for (int i = 0; i < 4; i++) {
            int idx = t + 256 * i;
            int row = idx >> 4;
            int c   = (idx & 15) * 4;
            *(float4*)&KVs[row * 68 + c] = *(const float4*)(Vt + row * DK + c);
        }

#pragma unroll
        for (int i = 0; i < 4; i++) {
            float tm = fmaxf(fmaxf(s[i][0], s[i][1]), fmaxf(s[i][2], s[i][3]));
#pragma unroll
            for (int off = 1; off < 16; off <<= 1)
                tm = fmaxf(tm, __shfl_xor_sync(0xffffffffu, tm, off));
            float mnew  = fmaxf(mrow[i], tm);
            float alpha = __expf(mrow[i] - mnew);
            mrow[i] = mnew;

            float p0 = __expf(s[i][0] - mnew);
            float p1 = __expf(s[i][1] - mnew);
            float p2 = __expf(s[i][2] - mnew);
            float p3 = __expf(s[i][3] - mnew);
            float rs = p0 + p1 + p2 + p3;
#pragma unroll
            for (int off = 1; off < 16; off <<= 1)
                rs += __shfl_xor_sync(0xffffffffu, rs, off);

            lrow[i] = lrow[i] * alpha + rs;
#pragma unroll
            for (int j = 0; j < 4; j++) acc[i][j] *= alpha;

            *(float4*)&Ps[(ty * 4 + i) * 64 + tx * 4] = make_float4(p0, p1, p2, p3);
        }
        __syncthreads();

#pragma unroll 8
        for (int kk = 0; kk < 64; kk++) {
            float4 v4 = *(float4*)&KVs[kk * 68 + tx * 4];
            float va[4] = {v4.x, v4.y, v4.z, v4.w};
            float pi[4];
#pragma unroll
            for (int i = 0; i < 4; i++) pi[i] = Ps[(ty * 4 + i) * 64 + kk];
#pragma unroll
            for (int i = 0; i < 4; i++)
#pragma unroll
                for (int j = 0; j < 4; j++)
                    acc[i][j] += pi[i] * va[j];
        }
    }

    // Normalize + write ctx [B,T,D] as bf16 hi/lo split
#pragma unroll
    for (int i = 0; i < 4; i++) {
        float inv = 1.f / lrow[i];
        int tok = qt * 64 + ty * 4 + i;
        size_t off = (size_t)(b * TSEQ + tok) * DMODEL + h * DK + tx * 4;
        float o[4] = {acc[i][0] * inv, acc[i][1] * inv,
                      acc[i][2] * inv, acc[i][3] * inv};
        __nv_bfloat16 hh[4], ll[4];
#pragma unroll
        for (int j = 0; j < 4; j++) {
            hh[j] = __float2bfloat16(o[j]);
            ll[j] = __float2bfloat16(o[j] - __bfloat162float(hh[j]));
        }
        __nv_bfloat162* ph = (__nv_bfloat162*)(g_ch + off);
        __nv_bfloat162* pl = (__nv_bfloat162*)(g_cl + off);
        ph[0] = __nv_bfloat162(hh[0], hh[1]); ph[1] = __nv_bfloat162(hh[2], hh[3]);
        pl[0] = __nv_bfloat162(ll[0], ll[1]); pl[1] = __nv_bfloat162(ll[2], ll[3]);
    }
}

// ===========================================================================
// Launch
// ===========================================================================
extern "C" void kernel_launch(void* const* d_in, const int* in_sizes, int n_in,
                              void* d_out, int out_size)
{
    const float* x  = (const float*)d_in[0];
    const float* Wq = (const float*)d_in[1];
    const float* bq = (const float*)d_in[2];
    const float* Wk = (const float*)d_in[3];
    const float* bk = (const float*)d_in[4];
    const float* Wv = (const float*)d_in[5];
    const float* bv = (const float*)d_in[6];
    const float* Wo = (const float*)d_in[7];
    const float* bo = (const float*)d_in[8];
    float* out = (float*)d_out;

    cudaFuncSetAttribute(mma_gemm_kernel,
                         cudaFuncAttributeMaxDynamicSharedMemorySize, GEMM_SMEM);
    cudaFuncSetAttribute(attn_kernel,
                         cudaFuncAttributeMaxDynamicSharedMemorySize, ATTN_SMEM);

    convert_kernel<<<dim3(4096, 5), 256>>>(x, Wq, Wk, Wv, Wo);

    mma_gemm_kernel<<<dim3(DMODEL / 64, MROWS / 128, 3), 256, GEMM_SMEM>>>(
        bq, bk, bv, nullptr, 0);

    attn_kernel<<<dim3(TSEQ / 64, NHEAD, BATCH), 256, ATTN_SMEM>>>();

    mma_gemm_kernel<<<dim3(DMODEL / 64, MROWS / 128, 1), 256, GEMM_SMEM>>>(
        bo, nullptr, nullptr, out, 1);
}